// round 12
// baseline (speedup 1.0000x reference)
#include <cuda_runtime.h>
#include <cuda_bf16.h>
#include <cstdint>

#define NB   16384
#define DIN  1024
#define NL   4
#define NK   1024
#define CB   512

// ---------------------------------------------------------------------------
// Device scratch (no cudaMalloc allowed); 16B aligned for cp.async/float4.
// ---------------------------------------------------------------------------
__device__ __align__(16) float g_residf[NB * CB];   // fp32 residual (exact chain)
__device__ __align__(16) int   g_ids[NB * NL];
__device__ __align__(16) float g_cnorm[NL * NK];
__device__ __align__(16) __nv_bfloat16 g_Ahi[NB * CB];        // bf16 hi of residual
__device__ __align__(16) __nv_bfloat16 g_Chi[NL * NK * CB];   // bf16 hi of codebooks
// encoder operands: 2-way bf16 splits (3 pair-terms: 00, 01, 10)
__device__ __align__(16) __nv_bfloat16 g_X0[NB * DIN];
__device__ __align__(16) __nv_bfloat16 g_X1[NB * DIN];
__device__ __align__(16) __nv_bfloat16 g_W0[CB * DIN];        // enc_W^T splits [n][k]
__device__ __align__(16) __nv_bfloat16 g_W1[CB * DIN];

// ---------------------------------------------------------------------------
// helpers
// ---------------------------------------------------------------------------
__device__ __forceinline__ uint32_t smem_u32(const void* p) {
    uint32_t a;
    asm("{ .reg .u64 t; cvta.to.shared.u64 t, %1; cvt.u32.u64 %0, t; }"
        : "=r"(a) : "l"(p));
    return a;
}
__device__ __forceinline__ void cpa16(uint32_t s, const void* g) {
    asm volatile("cp.async.cg.shared.global [%0], [%1], 16;" :: "r"(s), "l"(g));
}
__device__ __forceinline__ uint32_t swz(uint32_t b) { return b ^ ((b >> 3) & 0x70); }

__device__ __forceinline__ void ldmA(uint32_t* a, uint32_t addr) {
    asm volatile("ldmatrix.sync.aligned.m8n8.x4.shared.b16 {%0,%1,%2,%3}, [%4];"
                 : "=r"(a[0]), "=r"(a[1]), "=r"(a[2]), "=r"(a[3]) : "r"(addr));
}
__device__ __forceinline__ void ldmB4(uint32_t* b, uint32_t addr) {
    asm volatile("ldmatrix.sync.aligned.m8n8.x4.shared.b16 {%0,%1,%2,%3}, [%4];"
                 : "=r"(b[0]), "=r"(b[1]), "=r"(b[2]), "=r"(b[3]) : "r"(addr));
}
__device__ __forceinline__ void mma16816(float* c, const uint32_t* a, const uint32_t* b) {
    asm volatile(
        "mma.sync.aligned.m16n8k16.row.col.f32.bf16.bf16.f32 "
        "{%0,%1,%2,%3}, {%4,%5,%6,%7}, {%8,%9}, {%0,%1,%2,%3};"
        : "+f"(c[0]), "+f"(c[1]), "+f"(c[2]), "+f"(c[3])
        : "r"(a[0]), "r"(a[1]), "r"(a[2]), "r"(a[3]), "r"(b[0]), "r"(b[1]));
}

#define WAIT_TAIL(p, N) do {                                                   \
    if ((p) < (N) - 2)      asm volatile("cp.async.wait_group 2;" ::: "memory"); \
    else if ((p) == (N) - 2) asm volatile("cp.async.wait_group 1;" ::: "memory"); \
    else                     asm volatile("cp.async.wait_group 0;" ::: "memory"); \
} while (0)

// ---------------------------------------------------------------------------
// Prep kernels
// ---------------------------------------------------------------------------
__global__ void cnorm_kernel(const float* __restrict__ codebooks) {
    int warp = (blockIdx.x * blockDim.x + threadIdx.x) >> 5;
    int lane = threadIdx.x & 31;
    if (warp >= NL * NK) return;
    const float* c = codebooks + (size_t)warp * CB;
    float s = 0.f;
    for (int t = lane; t < CB; t += 32) { float v = c[t]; s += v * v; }
    #pragma unroll
    for (int o = 16; o > 0; o >>= 1) s += __shfl_xor_sync(0xffffffffu, s, o);
    if (lane == 0) g_cnorm[warp] = s;
}

__global__ void xsplit_kernel(const float* __restrict__ X) {
    int i = blockIdx.x * blockDim.x + threadIdx.x;
    if (i >= NB * DIN) return;
    float v = X[i];
    __nv_bfloat16 s0 = __float2bfloat16(v);
    __nv_bfloat16 s1 = __float2bfloat16(v - __bfloat162float(s0));
    g_X0[i] = s0; g_X1[i] = s1;
}

__global__ void cbhi_kernel(const float* __restrict__ Cbs) {
    int i = blockIdx.x * blockDim.x + threadIdx.x;
    if (i >= NL * NK * CB) return;
    g_Chi[i] = __float2bfloat16(Cbs[i]);
}

__global__ void wsplitT_kernel(const float* __restrict__ W) {  // [DIN][CB] -> [CB][DIN]
    int i = blockIdx.x * blockDim.x + threadIdx.x;
    if (i >= CB * DIN) return;
    int n = i / DIN, k = i % DIN;
    float v = W[(size_t)k * CB + n];
    __nv_bfloat16 s0 = __float2bfloat16(v);
    __nv_bfloat16 s1 = __float2bfloat16(v - __bfloat162float(s0));
    g_W0[i] = s0; g_W1[i] = s1;
}

// ---------------------------------------------------------------------------
// Encoder: r0 = X @ W + b via 3-pair bf16 split on mma.sync (err ~1e-4 abs)
// CTA tile 128x128, 16 warps (4m x 4n), warp tile 32x32. 48 K-chunks of 64.
// 4-stage cp.async pipeline, one barrier per chunk.
// ---------------------------------------------------------------------------
__global__ __launch_bounds__(512) void enc_mma_kernel(const float* __restrict__ encb) {
    extern __shared__ char dsm[];
    const uint32_t sb = smem_u32(dsm);
    // stages: A at sb + s*16384, B at sb + 65536 + s*16384
    const int tid = threadIdx.x, wid = tid >> 5, lane = tid & 31;
    const int wm = wid >> 2, wn = wid & 3;
    const int g = lane >> 2, q = lane & 3;
    const int m0 = blockIdx.y * 128, n0 = blockIdx.x * 128;

    const __nv_bfloat16* TA[3] = { g_X0, g_X0, g_X1 };
    const __nv_bfloat16* TB[3] = { g_W0, g_W1, g_W0 };

    float acc[2][4][4];
    #pragma unroll
    for (int i = 0; i < 2; i++)
        #pragma unroll
        for (int j = 0; j < 4; j++)
            #pragma unroll
            for (int k = 0; k < 4; k++) acc[i][j][k] = 0.f;

    auto issue = [&](int p) {
        int s = p & 3;
        int term = p >> 4, k0 = (p & 15) * 64;
        const __nv_bfloat16* As = TA[term];
        const __nv_bfloat16* Bs = TB[term];
        uint32_t ab = sb + s * 16384, bb = sb + 65536 + s * 16384;
        #pragma unroll
        for (int it = 0; it < 2; it++) {
            int w = tid + it * 512;
            int row = w >> 3, sg = w & 7;
            cpa16(ab + swz((uint32_t)(row * 128 + sg * 16)),
                  As + (size_t)(m0 + row) * DIN + k0 + sg * 8);
        }
        #pragma unroll
        for (int it = 0; it < 2; it++) {
            int w = tid + it * 512;
            int row = w >> 3, sg = w & 7;
            cpa16(bb + swz((uint32_t)(row * 128 + sg * 16)),
                  Bs + (size_t)(n0 + row) * DIN + k0 + sg * 8);
        }
        asm volatile("cp.async.commit_group;");
    };

    issue(0); issue(1); issue(2);

    #pragma unroll 1
    for (int p = 0; p < 48; p++) {
        WAIT_TAIL(p, 48);
        __syncthreads();
        if (p + 3 < 48) issue(p + 3);

        const uint32_t ab = sb + (p & 3) * 16384;
        const uint32_t bb = sb + 65536 + (p & 3) * 16384;
        #pragma unroll
        for (int kf = 0; kf < 4; kf++) {
            uint32_t af[2][4], bf[4][2];
            #pragma unroll
            for (int mf = 0; mf < 2; mf++) {
                int arow = wm * 32 + mf * 16 + (lane & 7) + ((lane >> 3) & 1) * 8;
                uint32_t koff = kf * 32 + (lane >> 4) * 16;
                ldmA(af[mf], ab + swz((uint32_t)(arow * 128) + koff));
            }
            #pragma unroll
            for (int np = 0; np < 2; np++) {
                uint32_t tmp[4];
                int nrow = wn * 32 + np * 16 + ((lane >> 4) & 1) * 8 + (lane & 7);
                uint32_t koff = kf * 32 + ((lane >> 3) & 1) * 16;
                ldmB4(tmp, bb + swz((uint32_t)(nrow * 128) + koff));
                bf[np * 2][0] = tmp[0]; bf[np * 2][1] = tmp[1];
                bf[np * 2 + 1][0] = tmp[2]; bf[np * 2 + 1][1] = tmp[3];
            }
            #pragma unroll
            for (int mf = 0; mf < 2; mf++)
                #pragma unroll
                for (int nf = 0; nf < 4; nf++)
                    mma16816(acc[mf][nf], af[mf], bf[nf]);
        }
    }

    // epilogue: bias + write fp32 residual and bf16 hi
    #pragma unroll
    for (int mf = 0; mf < 2; mf++) {
        #pragma unroll
        for (int nf = 0; nf < 4; nf++) {
            #pragma unroll
            for (int j = 0; j < 4; j++) {
                int row = m0 + wm * 32 + mf * 16 + g + (j >> 1) * 8;
                int col = n0 + wn * 32 + nf * 8 + q * 2 + (j & 1);
                float v = acc[mf][nf][j] + __ldg(&encb[col]);
                size_t o = (size_t)row * CB + col;
                g_residf[o] = v;
                g_Ahi[o]    = __float2bfloat16(v);
            }
        }
    }
}

// ---------------------------------------------------------------------------
// VQ layer: coarse bf16 scores (mma.sync) + top-3/owner + exact fp32 rescore.
// A (128x512 bf16) persistent in smem; B 4-stage pipeline, 1 barrier/chunk.
// ---------------------------------------------------------------------------
__global__ __launch_bounds__(512) void vq_layer_kernel(const float* __restrict__ cbs,
                                                       int layer) {
    extern __shared__ char dsm[];
    const uint32_t sb    = smem_u32(dsm);
    const uint32_t A_off = sb;                 // 8 tiles x 16KB = 128KB
    const uint32_t B_off = sb + 131072;        // 4 stages x 16KB
    float* red_d = (float*)dsm;                // [128][48] aliases A (used after loop)
    int*   red_i = (int*)(dsm + 128 * 48 * 4);
    __shared__ int bsel[128];

    const int tid = threadIdx.x, wid = tid >> 5, lane = tid & 31;
    const int wm = wid >> 2, wn = wid & 3;
    const int g = lane >> 2, q = lane & 3;
    const int m0 = blockIdx.x * 128;

    const __nv_bfloat16* Chi = g_Chi + (size_t)layer * NK * CB;
    const float* cn  = g_cnorm + layer * NK;
    const float* CbL = cbs + (size_t)layer * NK * CB;

    // A load: one commit group (group 0)
    #pragma unroll 1
    for (int it = 0; it < 16; it++) {
        int s = tid + it * 512;              // 0..8191 sectors
        int tile = s >> 10, w = s & 1023;
        int row = w >> 3, sg = w & 7;
        cpa16(A_off + tile * 16384 + swz((uint32_t)(row * 128 + sg * 16)),
              g_Ahi + (size_t)(m0 + row) * CB + tile * 64 + sg * 8);
    }
    asm volatile("cp.async.commit_group;");

    auto issueB = [&](int c) {
        int s = c & 3;
        int nt = c >> 3, kc = c & 7;
        uint32_t bb = B_off + s * 16384;
        #pragma unroll
        for (int it = 0; it < 2; it++) {
            int w = tid + it * 512;
            int row = w >> 3, sg = w & 7;
            cpa16(bb + swz((uint32_t)(row * 128 + sg * 16)),
                  Chi + (size_t)(nt * 128 + row) * CB + kc * 64 + sg * 8);
        }
        asm volatile("cp.async.commit_group;");
    };

    issueB(0); issueB(1); issueB(2);

    float t3d[4][3]; int t3i[4][3];
    #pragma unroll
    for (int r = 0; r < 4; r++) {
        t3d[r][0] = t3d[r][1] = t3d[r][2] = 3.4e38f;
        t3i[r][0] = t3i[r][1] = t3i[r][2] = 0;
    }

    float acc[2][4][4];

    #pragma unroll 1
    for (int p = 0; p < 64; p++) {
        const int nt = p >> 3, kc = p & 7;
        // groups: A + chunks; allowed pending 2 until near tail
        WAIT_TAIL(p, 64);
        __syncthreads();
        if (p + 3 < 64) issueB(p + 3);

        if (kc == 0) {
            #pragma unroll
            for (int i = 0; i < 2; i++)
                #pragma unroll
                for (int j = 0; j < 4; j++)
                    #pragma unroll
                    for (int k = 0; k < 4; k++) acc[i][j][k] = 0.f;
        }

        const uint32_t ab = A_off + kc * 16384;
        const uint32_t bb = B_off + (p & 3) * 16384;
        #pragma unroll
        for (int kf = 0; kf < 4; kf++) {
            uint32_t af[2][4], bf[4][2];
            #pragma unroll
            for (int mf = 0; mf < 2; mf++) {
                int arow = wm * 32 + mf * 16 + (lane & 7) + ((lane >> 3) & 1) * 8;
                uint32_t koff = kf * 32 + (lane >> 4) * 16;
                ldmA(af[mf], ab + swz((uint32_t)(arow * 128) + koff));
            }
            #pragma unroll
            for (int np = 0; np < 2; np++) {
                uint32_t tmp[4];
                int nrow = wn * 32 + np * 16 + ((lane >> 4) & 1) * 8 + (lane & 7);
                uint32_t koff = kf * 32 + ((lane >> 3) & 1) * 16;
                ldmB4(tmp, bb + swz((uint32_t)(nrow * 128) + koff));
                bf[np * 2][0] = tmp[0]; bf[np * 2][1] = tmp[1];
                bf[np * 2 + 1][0] = tmp[2]; bf[np * 2 + 1][1] = tmp[3];
            }
            #pragma unroll
            for (int mf = 0; mf < 2; mf++)
                #pragma unroll
                for (int nf = 0; nf < 4; nf++)
                    mma16816(acc[mf][nf], af[mf], bf[nf]);
        }

        if (kc == 7) {   // fold this code tile into per-thread top-3
            #pragma unroll
            for (int mf = 0; mf < 2; mf++) {
                #pragma unroll
                for (int nf = 0; nf < 4; nf++) {
                    int colbase = nt * 128 + wn * 32 + nf * 8 + q * 2;
                    #pragma unroll
                    for (int j = 0; j < 4; j++) {
                        int code = colbase + (j & 1);
                        float d = __ldg(&cn[code]) - 2.f * acc[mf][nf][j];
                        int rs = mf * 2 + (j >> 1);
                        if (d < t3d[rs][2]) {
                            if (d < t3d[rs][1]) {
                                t3d[rs][2] = t3d[rs][1]; t3i[rs][2] = t3i[rs][1];
                                if (d < t3d[rs][0]) {
                                    t3d[rs][1] = t3d[rs][0]; t3i[rs][1] = t3i[rs][0];
                                    t3d[rs][0] = d; t3i[rs][0] = code;
                                } else { t3d[rs][1] = d; t3i[rs][1] = code; }
                            } else { t3d[rs][2] = d; t3i[rs][2] = code; }
                        }
                    }
                }
            }
        }
    }
    __syncthreads();   // all MMA/A reads done before red_d aliases A region

    // dump per-owner top-3 (A smem region is free now)
    #pragma unroll
    for (int rs = 0; rs < 4; rs++) {
        int mf = rs >> 1, h = rs & 1;
        int row = wm * 32 + mf * 16 + g + h * 8;
        int owner = wn * 4 + q;               // 0..15
        #pragma unroll
        for (int j = 0; j < 3; j++) {
            red_d[row * 48 + owner * 3 + j] = t3d[rs][j];
            red_i[row * 48 + owner * 3 + j] = t3i[rs][j];
        }
    }
    __syncthreads();

    // exact fp32 rescore within margin of coarse min: 4 threads per row
    {
        int row = tid >> 2, sub = tid & 3;    // 512 threads -> 128 rows x 4
        const float* rd = red_d + row * 48;
        const int*   ri = red_i + row * 48;
        float lmin = 3.4e38f;
        #pragma unroll 1
        for (int e = sub * 12; e < sub * 12 + 12; e++) lmin = fminf(lmin, rd[e]);
        #pragma unroll
        for (int o = 1; o < 4; o <<= 1) lmin = fminf(lmin, __shfl_xor_sync(0xffffffffu, lmin, o));
        const float TAU = 1.5f;
        float bd = 3.4e38f; int bi = 0x7fffffff;
        const float* R = g_residf + (size_t)(m0 + row) * CB;
        #pragma unroll 1
        for (int e = sub * 12; e < sub * 12 + 12; e++) {
            if (rd[e] <= lmin + TAU) {
                int c = ri[e];
                const float* C = CbL + (size_t)c * CB;
                float s0 = 0.f, s1 = 0.f, s2 = 0.f, s3 = 0.f;
                #pragma unroll 4
                for (int k = 0; k < CB; k += 4) {
                    s0 += R[k]     * C[k];
                    s1 += R[k + 1] * C[k + 1];
                    s2 += R[k + 2] * C[k + 2];
                    s3 += R[k + 3] * C[k + 3];
                }
                float de = __ldg(&cn[c]) - 2.f * ((s0 + s1) + (s2 + s3));
                if (de < bd || (de == bd && c < bi)) { bd = de; bi = c; }
            }
        }
        #pragma unroll
        for (int o = 1; o < 4; o <<= 1) {
            float od = __shfl_xor_sync(0xffffffffu, bd, o);
            int   oi = __shfl_xor_sync(0xffffffffu, bi, o);
            if (od < bd || (od == bd && oi < bi)) { bd = od; bi = oi; }
        }
        if (sub == 0) {
            bsel[row] = bi;
            g_ids[(size_t)(m0 + row) * NL + layer] = bi;
        }
    }
    __syncthreads();

    // residual -= codebook[best]; store fp32 + bf16 hi for next layer
    #pragma unroll 1
    for (int e = tid; e < 128 * (CB / 4); e += 512) {
        int r = e >> 7, c4 = (e & 127) * 4;
        int ci = bsel[r];
        size_t ro = (size_t)(m0 + r) * CB + c4;
        float4 rv = *(float4*)&g_residf[ro];
        float4 cv = *(const float4*)&CbL[(size_t)ci * CB + c4];
        rv.x -= cv.x; rv.y -= cv.y; rv.z -= cv.z; rv.w -= cv.w;
        *(float4*)&g_residf[ro] = rv;
        if (layer < NL - 1) {
            __nv_bfloat162 h0{__float2bfloat16(rv.x), __float2bfloat16(rv.y)};
            __nv_bfloat162 h1{__float2bfloat16(rv.z), __float2bfloat16(rv.w)};
            *(__nv_bfloat162*)&g_Ahi[ro]     = h0;
            *(__nv_bfloat162*)&g_Ahi[ro + 2] = h1;
        }
    }
}

// ---------------------------------------------------------------------------
// Decoder + ids output (exact, unchanged from passing baseline)
// ---------------------------------------------------------------------------
__global__ void decode_kernel(const float* __restrict__ dec_W,
                              const float* __restrict__ dec_b,
                              float* __restrict__ out) {
    int idx = blockIdx.x * blockDim.x + threadIdx.x;
    if (idx >= NB * CB) return;
    int b = idx / CB, j = idx % CB;
    const int* ids = &g_ids[b * NL];
    float s = dec_b[j];
    #pragma unroll
    for (int l = 0; l < NL; l++)
        s += (float)ids[l] * dec_W[l * CB + j];
    out[idx] = s;
}

__global__ void ids_out_kernel(float* __restrict__ out, int n) {
    int idx = blockIdx.x * blockDim.x + threadIdx.x;
    if (idx < n) out[idx] = (float)g_ids[idx];
}

// ---------------------------------------------------------------------------
extern "C" void kernel_launch(void* const* d_in, const int* in_sizes, int n_in,
                              void* d_out, int out_size) {
    (void)in_sizes; (void)n_in;
    const float* X    = (const float*)d_in[0];
    const float* encW = (const float*)d_in[1];
    const float* encb = (const float*)d_in[2];
    const float* cbs  = (const float*)d_in[3];
    const float* decW = (const float*)d_in[4];
    const float* decb = (const float*)d_in[5];
    float* out = (float*)d_out;

    const int VQ_SMEM  = 131072 + 4 * 16384;   // 196608
    const int ENC_SMEM = 8 * 16384;            // 131072
    cudaFuncSetAttribute(vq_layer_kernel, cudaFuncAttributeMaxDynamicSharedMemorySize, VQ_SMEM);
    cudaFuncSetAttribute(enc_mma_kernel,  cudaFuncAttributeMaxDynamicSharedMemorySize, ENC_SMEM);

    // prep
    cnorm_kernel<<<(NL * NK * 32 + 255) / 256, 256>>>(cbs);
    xsplit_kernel<<<(NB * DIN + 255) / 256, 256>>>(X);
    cbhi_kernel<<<(NL * NK * CB + 255) / 256, 256>>>(cbs);
    wsplitT_kernel<<<(CB * DIN + 255) / 256, 256>>>(encW);

    // encoder (tensor cores, 3-pair split)
    dim3 gEnc(CB / 128, NB / 128);
    enc_mma_kernel<<<gEnc, 512, ENC_SMEM>>>(encb);

    // VQ layers (tensor-core coarse + exact rescore)
    for (int l = 0; l < NL; l++)
        vq_layer_kernel<<<NB / 128, 512, VQ_SMEM>>>(cbs, l);

    const long long RE = (long long)NB * CB;   // 8388608
    const long long ID = (long long)NB * NL;   // 65536

    if ((long long)out_size >= RE) {
        decode_kernel<<<(NB * CB + 255) / 256, 256>>>(decW, decb, out);
        if ((long long)out_size >= RE + ID)
            ids_out_kernel<<<(int)((ID + 255) / 256), 256>>>(out + RE, (int)ID);
    } else {
        ids_out_kernel<<<(out_size + 255) / 256, 256>>>(out, out_size);
    }
}

// round 16
// speedup vs baseline: 1.0683x; 1.0683x over previous
#include <cuda_runtime.h>
#include <cuda_bf16.h>
#include <cstdint>

#define NB   16384
#define DIN  1024
#define NL   4
#define NK   1024
#define CB   512

// ---------------------------------------------------------------------------
// Device scratch (no cudaMalloc allowed); 16B aligned for cp.async/float4.
// ---------------------------------------------------------------------------
__device__ __align__(16) float g_residf[NB * CB];   // fp32 residual (exact chain)
__device__ __align__(16) int   g_ids[NB * NL];
__device__ __align__(16) float g_cnorm[NL * NK];
__device__ __align__(16) __nv_bfloat16 g_Ahi[NB * CB];        // bf16 hi of residual
__device__ __align__(16) __nv_bfloat16 g_Chi[NL * NK * CB];   // bf16 hi of codebooks
// encoder operands: 2-way bf16 splits (3 pair-terms: 00, 01, 10)
__device__ __align__(16) __nv_bfloat16 g_X0[NB * DIN];
__device__ __align__(16) __nv_bfloat16 g_X1[NB * DIN];
__device__ __align__(16) __nv_bfloat16 g_W0[CB * DIN];        // enc_W^T splits [n][k]
__device__ __align__(16) __nv_bfloat16 g_W1[CB * DIN];

// ---------------------------------------------------------------------------
// helpers
// ---------------------------------------------------------------------------
__device__ __forceinline__ uint32_t smem_u32(const void* p) {
    uint32_t a;
    asm("{ .reg .u64 t; cvta.to.shared.u64 t, %1; cvt.u32.u64 %0, t; }"
        : "=r"(a) : "l"(p));
    return a;
}
__device__ __forceinline__ void cpa16(uint32_t s, const void* g) {
    asm volatile("cp.async.cg.shared.global [%0], [%1], 16;" :: "r"(s), "l"(g));
}
__device__ __forceinline__ uint32_t swz(uint32_t b) { return b ^ ((b >> 3) & 0x70); }

__device__ __forceinline__ void ldmA(uint32_t* a, uint32_t addr) {
    asm volatile("ldmatrix.sync.aligned.m8n8.x4.shared.b16 {%0,%1,%2,%3}, [%4];"
                 : "=r"(a[0]), "=r"(a[1]), "=r"(a[2]), "=r"(a[3]) : "r"(addr));
}
__device__ __forceinline__ void ldmB4(uint32_t* b, uint32_t addr) {
    asm volatile("ldmatrix.sync.aligned.m8n8.x4.shared.b16 {%0,%1,%2,%3}, [%4];"
                 : "=r"(b[0]), "=r"(b[1]), "=r"(b[2]), "=r"(b[3]) : "r"(addr));
}
__device__ __forceinline__ void mma16816(float* c, const uint32_t* a, const uint32_t* b) {
    asm volatile(
        "mma.sync.aligned.m16n8k16.row.col.f32.bf16.bf16.f32 "
        "{%0,%1,%2,%3}, {%4,%5,%6,%7}, {%8,%9}, {%0,%1,%2,%3};"
        : "+f"(c[0]), "+f"(c[1]), "+f"(c[2]), "+f"(c[3])
        : "r"(a[0]), "r"(a[1]), "r"(a[2]), "r"(a[3]), "r"(b[0]), "r"(b[1]));
}

#define WAIT_TAIL(p, N) do {                                                   \
    if ((p) < (N) - 2)      asm volatile("cp.async.wait_group 2;" ::: "memory"); \
    else if ((p) == (N) - 2) asm volatile("cp.async.wait_group 1;" ::: "memory"); \
    else                     asm volatile("cp.async.wait_group 0;" ::: "memory"); \
} while (0)

// ---------------------------------------------------------------------------
// Prep kernels (merged: 2 launches total)
// ---------------------------------------------------------------------------
__global__ void split_xw_kernel(const float* __restrict__ X,
                                const float* __restrict__ W) {
    int i = blockIdx.x * blockDim.x + threadIdx.x;
    if (i < NB * DIN) {
        float v = X[i];
        __nv_bfloat16 s0 = __float2bfloat16(v);
        __nv_bfloat16 s1 = __float2bfloat16(v - __bfloat162float(s0));
        g_X0[i] = s0; g_X1[i] = s1;
    }
    if (i < CB * DIN) {                       // enc_W^T splits
        int n = i / DIN, k = i % DIN;
        float v = W[(size_t)k * CB + n];
        __nv_bfloat16 s0 = __float2bfloat16(v);
        __nv_bfloat16 s1 = __float2bfloat16(v - __bfloat162float(s0));
        g_W0[i] = s0; g_W1[i] = s1;
    }
}

__global__ void prep_cb_kernel(const float* __restrict__ Cbs) {
    int i = blockIdx.x * blockDim.x + threadIdx.x;
    if (i < NL * NK * CB) g_Chi[i] = __float2bfloat16(Cbs[i]);
    int warp = i >> 5;
    int lane = threadIdx.x & 31;
    if (warp < NL * NK) {
        const float* c = Cbs + (size_t)warp * CB;
        float s = 0.f;
        for (int t = lane; t < CB; t += 32) { float v = c[t]; s += v * v; }
        #pragma unroll
        for (int o = 16; o > 0; o >>= 1) s += __shfl_xor_sync(0xffffffffu, s, o);
        if (lane == 0) g_cnorm[warp] = s;
    }
}

// ---------------------------------------------------------------------------
// Encoder: r0 = X @ W + b via 3-pair bf16 split on mma.sync (err ~1e-5 rel)
// CTA tile 128x128, 16 warps (4m x 4n), warp tile 32x32. 48 K-chunks of 64.
// 4-stage cp.async pipeline, one barrier per chunk. (identical to passing R12)
// ---------------------------------------------------------------------------
__global__ __launch_bounds__(512) void enc_mma_kernel(const float* __restrict__ encb) {
    extern __shared__ char dsm[];
    const uint32_t sb = smem_u32(dsm);
    const int tid = threadIdx.x, wid = tid >> 5, lane = tid & 31;
    const int wm = wid >> 2, wn = wid & 3;
    const int g = lane >> 2, q = lane & 3;
    const int m0 = blockIdx.y * 128, n0 = blockIdx.x * 128;

    const __nv_bfloat16* TA[3] = { g_X0, g_X0, g_X1 };
    const __nv_bfloat16* TB[3] = { g_W0, g_W1, g_W0 };

    float acc[2][4][4];
    #pragma unroll
    for (int i = 0; i < 2; i++)
        #pragma unroll
        for (int j = 0; j < 4; j++)
            #pragma unroll
            for (int k = 0; k < 4; k++) acc[i][j][k] = 0.f;

    auto issue = [&](int p) {
        int s = p & 3;
        int term = p >> 4, k0 = (p & 15) * 64;
        const __nv_bfloat16* As = TA[term];
        const __nv_bfloat16* Bs = TB[term];
        uint32_t ab = sb + s * 16384, bb = sb + 65536 + s * 16384;
        #pragma unroll
        for (int it = 0; it < 2; it++) {
            int w = tid + it * 512;
            int row = w >> 3, sg = w & 7;
            cpa16(ab + swz((uint32_t)(row * 128 + sg * 16)),
                  As + (size_t)(m0 + row) * DIN + k0 + sg * 8);
        }
        #pragma unroll
        for (int it = 0; it < 2; it++) {
            int w = tid + it * 512;
            int row = w >> 3, sg = w & 7;
            cpa16(bb + swz((uint32_t)(row * 128 + sg * 16)),
                  Bs + (size_t)(n0 + row) * DIN + k0 + sg * 8);
        }
        asm volatile("cp.async.commit_group;");
    };

    issue(0); issue(1); issue(2);

    #pragma unroll 1
    for (int p = 0; p < 48; p++) {
        WAIT_TAIL(p, 48);
        __syncthreads();
        if (p + 3 < 48) issue(p + 3);

        const uint32_t ab = sb + (p & 3) * 16384;
        const uint32_t bb = sb + 65536 + (p & 3) * 16384;
        #pragma unroll
        for (int kf = 0; kf < 4; kf++) {
            uint32_t af[2][4], bf[4][2];
            #pragma unroll
            for (int mf = 0; mf < 2; mf++) {
                int arow = wm * 32 + mf * 16 + (lane & 7) + ((lane >> 3) & 1) * 8;
                uint32_t koff = kf * 32 + (lane >> 4) * 16;
                ldmA(af[mf], ab + swz((uint32_t)(arow * 128) + koff));
            }
            #pragma unroll
            for (int np = 0; np < 2; np++) {
                uint32_t tmp[4];
                int nrow = wn * 32 + np * 16 + ((lane >> 4) & 1) * 8 + (lane & 7);
                uint32_t koff = kf * 32 + ((lane >> 3) & 1) * 16;
                ldmB4(tmp, bb + swz((uint32_t)(nrow * 128) + koff));
                bf[np * 2][0] = tmp[0]; bf[np * 2][1] = tmp[1];
                bf[np * 2 + 1][0] = tmp[2]; bf[np * 2 + 1][1] = tmp[3];
            }
            #pragma unroll
            for (int mf = 0; mf < 2; mf++)
                #pragma unroll
                for (int nf = 0; nf < 4; nf++)
                    mma16816(acc[mf][nf], af[mf], bf[nf]);
        }
    }

    // epilogue: bias + write fp32 residual and bf16 hi
    #pragma unroll
    for (int mf = 0; mf < 2; mf++) {
        #pragma unroll
        for (int nf = 0; nf < 4; nf++) {
            #pragma unroll
            for (int j = 0; j < 4; j++) {
                int row = m0 + wm * 32 + mf * 16 + g + (j >> 1) * 8;
                int col = n0 + wn * 32 + nf * 8 + q * 2 + (j & 1);
                float v = acc[mf][nf][j] + __ldg(&encb[col]);
                size_t o = (size_t)row * CB + col;
                g_residf[o] = v;
                g_Ahi[o]    = __float2bfloat16(v);
            }
        }
    }
}

// ---------------------------------------------------------------------------
// Fused 4-layer VQ kernel. Each CTA owns 128 rows for the whole chain.
// Per layer (all R12-proven mechanics):
//   - reload A (bf16 residual hi) from g_Ahi via cp.async
//   - coarse bf16 scores (mma.sync), B 2-stage pipeline
//   - per-thread top-3, dump into red smem (aliases A region)
//   - exact fp32 rescore within margin (reads g_residf)
//   - residual update: fp32 -> g_residf, bf16 hi -> g_Ahi (global)
// smem: A 8x16KB = 128KB | B 2x16KB = 32KB  (total 163840)
// ---------------------------------------------------------------------------
__global__ __launch_bounds__(512) void vq_fused_kernel(const float* __restrict__ cbs) {
    extern __shared__ char dsm[];
    const uint32_t sb    = smem_u32(dsm);
    const uint32_t A_off = sb;                       // 8 tiles x 16KB
    const uint32_t B_off = sb + 131072;              // 2 stages x 16KB
    float* red_d = (float*)dsm;                      // [128][48] aliases A
    int*   red_i = (int*)(dsm + 128 * 48 * 4);       // [128][48] aliases A
    __shared__ int bsel[128];

    const int tid = threadIdx.x, wid = tid >> 5, lane = tid & 31;
    const int wm = wid >> 2, wn = wid & 3;
    const int g = lane >> 2, q = lane & 3;
    const int m0 = blockIdx.x * 128;

    #pragma unroll 1
    for (int layer = 0; layer < NL; layer++) {
        const __nv_bfloat16* Chi = g_Chi + (size_t)layer * NK * CB;
        const float* cn  = g_cnorm + layer * NK;
        const float* CbL = cbs + (size_t)layer * NK * CB;

        // A load from g_Ahi: one commit group
        #pragma unroll 1
        for (int it = 0; it < 16; it++) {
            int s = tid + it * 512;
            int tile = s >> 10, w = s & 1023;
            int row = w >> 3, sg = w & 7;
            cpa16(A_off + tile * 16384 + swz((uint32_t)(row * 128 + sg * 16)),
                  g_Ahi + (size_t)(m0 + row) * CB + tile * 64 + sg * 8);
        }
        asm volatile("cp.async.commit_group;");

        auto issueB = [&](int c) {
            uint32_t bb = B_off + (c & 1) * 16384;
            int nt = c >> 3, kc = c & 7;
            #pragma unroll
            for (int it = 0; it < 2; it++) {
                int w = tid + it * 512;
                int row = w >> 3, sg = w & 7;
                cpa16(bb + swz((uint32_t)(row * 128 + sg * 16)),
                      Chi + (size_t)(nt * 128 + row) * CB + kc * 64 + sg * 8);
            }
            asm volatile("cp.async.commit_group;");
        };

        issueB(0); issueB(1);

        float t3d[4][3]; int t3i[4][3];
        #pragma unroll
        for (int r = 0; r < 4; r++) {
            t3d[r][0] = t3d[r][1] = t3d[r][2] = 3.4e38f;
            t3i[r][0] = t3i[r][1] = t3i[r][2] = 0;
        }

        float acc[2][4][4];

        #pragma unroll 1
        for (int p = 0; p < 64; p++) {
            const int nt = p >> 3, kc = p & 7;
            if (p == 63) asm volatile("cp.async.wait_group 0;" ::: "memory");
            else         asm volatile("cp.async.wait_group 1;" ::: "memory");
            __syncthreads();

            if (kc == 0) {
                #pragma unroll
                for (int i = 0; i < 2; i++)
                    #pragma unroll
                    for (int j = 0; j < 4; j++)
                        #pragma unroll
                        for (int k = 0; k < 4; k++) acc[i][j][k] = 0.f;
            }

            const uint32_t ab = A_off + kc * 16384;
            const uint32_t bb = B_off + (p & 1) * 16384;
            #pragma unroll
            for (int kf = 0; kf < 4; kf++) {
                uint32_t af[2][4], bf[4][2];
                #pragma unroll
                for (int mf = 0; mf < 2; mf++) {
                    int arow = wm * 32 + mf * 16 + (lane & 7) + ((lane >> 3) & 1) * 8;
                    uint32_t koff = kf * 32 + (lane >> 4) * 16;
                    ldmA(af[mf], ab + swz((uint32_t)(arow * 128) + koff));
                }
                #pragma unroll
                for (int np = 0; np < 2; np++) {
                    uint32_t tmp[4];
                    int nrow = wn * 32 + np * 16 + ((lane >> 4) & 1) * 8 + (lane & 7);
                    uint32_t koff = kf * 32 + ((lane >> 3) & 1) * 16;
                    ldmB4(tmp, bb + swz((uint32_t)(nrow * 128) + koff));
                    bf[np * 2][0] = tmp[0]; bf[np * 2][1] = tmp[1];
                    bf[np * 2 + 1][0] = tmp[2]; bf[np * 2 + 1][1] = tmp[3];
                }
                #pragma unroll
                for (int mf = 0; mf < 2; mf++)
                    #pragma unroll
                    for (int nf = 0; nf < 4; nf++)
                        mma16816(acc[mf][nf], af[mf], bf[nf]);
            }

            if (kc == 7) {   // fold this 128-code tile into per-thread top-3
                #pragma unroll
                for (int mf = 0; mf < 2; mf++) {
                    #pragma unroll
                    for (int nf = 0; nf < 4; nf++) {
                        int colbase = nt * 128 + wn * 32 + nf * 8 + q * 2;
                        #pragma unroll
                        for (int j = 0; j < 4; j++) {
                            int code = colbase + (j & 1);
                            float d = __ldg(&cn[code]) - 2.f * acc[mf][nf][j];
                            int rs = mf * 2 + (j >> 1);
                            if (d < t3d[rs][2]) {
                                if (d < t3d[rs][1]) {
                                    t3d[rs][2] = t3d[rs][1]; t3i[rs][2] = t3i[rs][1];
                                    if (d < t3d[rs][0]) {
                                        t3d[rs][1] = t3d[rs][0]; t3i[rs][1] = t3i[rs][0];
                                        t3d[rs][0] = d; t3i[rs][0] = code;
                                    } else { t3d[rs][1] = d; t3i[rs][1] = code; }
                                } else { t3d[rs][2] = d; t3i[rs][2] = code; }
                            }
                        }
                    }
                }
            }
            __syncthreads();                 // all reads of consumed stage done
            if (p + 2 < 64) issueB(p + 2);   // refill the stage just consumed
        }
        __syncthreads();   // all MMA/A reads done before red aliases A region

        // dump per-owner top-3 (A smem region is free; reloaded next layer)
        #pragma unroll
        for (int rs = 0; rs < 4; rs++) {
            int mf = rs >> 1, h = rs & 1;
            int row = wm * 32 + mf * 16 + g + h * 8;
            int owner = wn * 4 + q;           // 0..15
            #pragma unroll
            for (int j = 0; j < 3; j++) {
                red_d[row * 48 + owner * 3 + j] = t3d[rs][j];
                red_i[row * 48 + owner * 3 + j] = t3i[rs][j];
            }
        }
        __syncthreads();

        // exact fp32 rescore within margin of coarse min: 4 threads per row
        {
            int row = tid >> 2, sub = tid & 3;
            const float* rd = red_d + row * 48;
            const int*   ri = red_i + row * 48;
            float lmin = 3.4e38f;
            #pragma unroll 1
            for (int e = sub * 12; e < sub * 12 + 12; e++) lmin = fminf(lmin, rd[e]);
            #pragma unroll
            for (int o = 1; o < 4; o <<= 1)
                lmin = fminf(lmin, __shfl_xor_sync(0xffffffffu, lmin, o));
            const float TAU = 1.5f;
            float bd = 3.4e38f; int bi = 0x7fffffff;
            const float* R = g_residf + (size_t)(m0 + row) * CB;
            #pragma unroll 1
            for (int e = sub * 12; e < sub * 12 + 12; e++) {
                if (rd[e] <= lmin + TAU) {
                    int c = ri[e];
                    const float* C = CbL + (size_t)c * CB;
                    float s0 = 0.f, s1 = 0.f, s2 = 0.f, s3 = 0.f;
                    #pragma unroll 4
                    for (int k = 0; k < CB; k += 4) {
                        s0 += R[k]     * C[k];
                        s1 += R[k + 1] * C[k + 1];
                        s2 += R[k + 2] * C[k + 2];
                        s3 += R[k + 3] * C[k + 3];
                    }
                    float de = __ldg(&cn[c]) - 2.f * ((s0 + s1) + (s2 + s3));
                    if (de < bd || (de == bd && c < bi)) { bd = de; bi = c; }
                }
            }
            #pragma unroll
            for (int o = 1; o < 4; o <<= 1) {
                float od = __shfl_xor_sync(0xffffffffu, bd, o);
                int   oi = __shfl_xor_sync(0xffffffffu, bi, o);
                if (od < bd || (od == bd && oi < bi)) { bd = od; bi = oi; }
            }
            if (sub == 0) {
                bsel[row] = bi;
                g_ids[(size_t)(m0 + row) * NL + layer] = bi;
            }
        }
        __syncthreads();

        // residual -= codebook[best]; fp32 + bf16 hi both to GLOBAL (as R12)
        #pragma unroll 1
        for (int e = tid; e < 128 * (CB / 4); e += 512) {
            int r = e >> 7, c4 = (e & 127) * 4;
            int ci = bsel[r];
            size_t ro = (size_t)(m0 + r) * CB + c4;
            float4 rv = *(float4*)&g_residf[ro];
            float4 cv = *(const float4*)&CbL[(size_t)ci * CB + c4];
            rv.x -= cv.x; rv.y -= cv.y; rv.z -= cv.z; rv.w -= cv.w;
            *(float4*)&g_residf[ro] = rv;
            if (layer < NL - 1) {
                __nv_bfloat162 h0{__float2bfloat16(rv.x), __float2bfloat16(rv.y)};
                __nv_bfloat162 h1{__float2bfloat16(rv.z), __float2bfloat16(rv.w)};
                *(__nv_bfloat162*)&g_Ahi[ro]     = h0;
                *(__nv_bfloat162*)&g_Ahi[ro + 2] = h1;
            }
        }
        __syncthreads();   // g_Ahi writes visible before next layer's A load
    }
}

// ---------------------------------------------------------------------------
// Decoder + ids output (exact)
// ---------------------------------------------------------------------------
__global__ void decode_kernel(const float* __restrict__ dec_W,
                              const float* __restrict__ dec_b,
                              float* __restrict__ out) {
    int idx = blockIdx.x * blockDim.x + threadIdx.x;
    if (idx >= NB * CB) return;
    int b = idx / CB, j = idx % CB;
    const int* ids = &g_ids[b * NL];
    float s = dec_b[j];
    #pragma unroll
    for (int l = 0; l < NL; l++)
        s += (float)ids[l] * dec_W[l * CB + j];
    out[idx] = s;
}

__global__ void ids_out_kernel(float* __restrict__ out, int n) {
    int idx = blockIdx.x * blockDim.x + threadIdx.x;
    if (idx < n) out[idx] = (float)g_ids[idx];
}

// ---------------------------------------------------------------------------
extern "C" void kernel_launch(void* const* d_in, const int* in_sizes, int n_in,
                              void* d_out, int out_size) {
    (void)in_sizes; (void)n_in;
    const float* X    = (const float*)d_in[0];
    const float* encW = (const float*)d_in[1];
    const float* encb = (const float*)d_in[2];
    const float* cbs  = (const float*)d_in[3];
    const float* decW = (const float*)d_in[4];
    const float* decb = (const float*)d_in[5];
    float* out = (float*)d_out;

    const int VQ_SMEM  = 131072 + 2 * 16384;   // 163840
    const int ENC_SMEM = 8 * 16384;            // 131072
    cudaFuncSetAttribute(vq_fused_kernel, cudaFuncAttributeMaxDynamicSharedMemorySize, VQ_SMEM);
    cudaFuncSetAttribute(enc_mma_kernel,  cudaFuncAttributeMaxDynamicSharedMemorySize, ENC_SMEM);

    // prep (2 launches)
    split_xw_kernel<<<(NB * DIN + 255) / 256, 256>>>(X, encW);
    prep_cb_kernel<<<(NL * NK * CB + 255) / 256, 256>>>(cbs);

    // encoder (tensor cores, 3-pair split)
    dim3 gEnc(CB / 128, NB / 128);
    enc_mma_kernel<<<gEnc, 512, ENC_SMEM>>>(encb);

    // fused 4-layer VQ (tensor-core coarse + exact rescore)
    vq_fused_kernel<<<NB / 128, 512, VQ_SMEM>>>(cbs);

    const long long RE = (long long)NB * CB;   // 8388608
    const long long ID = (long long)NB * NL;   // 65536

    if ((long long)out_size >= RE) {
        decode_kernel<<<(NB * CB + 255) / 256, 256>>>(decW, decb, out);
        if ((long long)out_size >= RE + ID)
            ids_out_kernel<<<(int)((ID + 255) / 256), 256>>>(out + RE, (int)ID);
    } else {
        ids_out_kernel<<<(out_size + 255) / 256, 256>>>(out, out_size);
    }
}

// round 17
// speedup vs baseline: 1.0915x; 1.0217x over previous
#include <cuda_runtime.h>
#include <cuda_bf16.h>
#include <cstdint>

#define NB   16384
#define DIN  1024
#define NL   4
#define NK   1024
#define CB   512

// ---------------------------------------------------------------------------
// Device scratch (no cudaMalloc allowed); 16B aligned for cp.async/float4.
// ---------------------------------------------------------------------------
__device__ __align__(16) float g_residf[NB * CB];   // fp32 residual (exact chain)
__device__ __align__(16) int   g_ids[NB * NL];
__device__ __align__(16) float g_cnorm[NL * NK];
__device__ __align__(16) __nv_bfloat16 g_Ahi[NB * CB];        // bf16 hi of residual
__device__ __align__(16) __nv_bfloat16 g_Chi[NL * NK * CB];   // bf16 hi of codebooks
// encoder operands: 2-way bf16 splits (3 pair-terms: 00, 01, 10)
__device__ __align__(16) __nv_bfloat16 g_X0[NB * DIN];
__device__ __align__(16) __nv_bfloat16 g_X1[NB * DIN];
__device__ __align__(16) __nv_bfloat16 g_W0[CB * DIN];        // enc_W^T splits [n][k]
__device__ __align__(16) __nv_bfloat16 g_W1[CB * DIN];

// ---------------------------------------------------------------------------
// helpers
// ---------------------------------------------------------------------------
__device__ __forceinline__ uint32_t smem_u32(const void* p) {
    uint32_t a;
    asm("{ .reg .u64 t; cvta.to.shared.u64 t, %1; cvt.u32.u64 %0, t; }"
        : "=r"(a) : "l"(p));
    return a;
}
__device__ __forceinline__ void cpa16(uint32_t s, const void* g) {
    asm volatile("cp.async.cg.shared.global [%0], [%1], 16;" :: "r"(s), "l"(g));
}
__device__ __forceinline__ uint32_t swz(uint32_t b) { return b ^ ((b >> 3) & 0x70); }

__device__ __forceinline__ void ldmA(uint32_t* a, uint32_t addr) {
    asm volatile("ldmatrix.sync.aligned.m8n8.x4.shared.b16 {%0,%1,%2,%3}, [%4];"
                 : "=r"(a[0]), "=r"(a[1]), "=r"(a[2]), "=r"(a[3]) : "r"(addr));
}
__device__ __forceinline__ void ldmB4(uint32_t* b, uint32_t addr) {
    asm volatile("ldmatrix.sync.aligned.m8n8.x4.shared.b16 {%0,%1,%2,%3}, [%4];"
                 : "=r"(b[0]), "=r"(b[1]), "=r"(b[2]), "=r"(b[3]) : "r"(addr));
}
__device__ __forceinline__ void mma16816(float* c, const uint32_t* a, const uint32_t* b) {
    asm volatile(
        "mma.sync.aligned.m16n8k16.row.col.f32.bf16.bf16.f32 "
        "{%0,%1,%2,%3}, {%4,%5,%6,%7}, {%8,%9}, {%0,%1,%2,%3};"
        : "+f"(c[0]), "+f"(c[1]), "+f"(c[2]), "+f"(c[3])
        : "r"(a[0]), "r"(a[1]), "r"(a[2]), "r"(a[3]), "r"(b[0]), "r"(b[1]));
}

#define WAIT_TAIL(p, N) do {                                                   \
    if ((p) < (N) - 2)      asm volatile("cp.async.wait_group 2;" ::: "memory"); \
    else if ((p) == (N) - 2) asm volatile("cp.async.wait_group 1;" ::: "memory"); \
    else                     asm volatile("cp.async.wait_group 0;" ::: "memory"); \
} while (0)

// ---------------------------------------------------------------------------
// Prep kernels (merged: 2 launches total)
// ---------------------------------------------------------------------------
__global__ void split_xw_kernel(const float* __restrict__ X,
                                const float* __restrict__ W) {
    int i = blockIdx.x * blockDim.x + threadIdx.x;
    if (i < NB * DIN) {
        float v = X[i];
        __nv_bfloat16 s0 = __float2bfloat16(v);
        __nv_bfloat16 s1 = __float2bfloat16(v - __bfloat162float(s0));
        g_X0[i] = s0; g_X1[i] = s1;
    }
    if (i < CB * DIN) {                       // enc_W^T splits
        int n = i / DIN, k = i % DIN;
        float v = W[(size_t)k * CB + n];
        __nv_bfloat16 s0 = __float2bfloat16(v);
        __nv_bfloat16 s1 = __float2bfloat16(v - __bfloat162float(s0));
        g_W0[i] = s0; g_W1[i] = s1;
    }
}

__global__ void prep_cb_kernel(const float* __restrict__ Cbs) {
    int i = blockIdx.x * blockDim.x + threadIdx.x;
    if (i < NL * NK * CB) g_Chi[i] = __float2bfloat16(Cbs[i]);
    int warp = i >> 5;
    int lane = threadIdx.x & 31;
    if (warp < NL * NK) {
        const float* c = Cbs + (size_t)warp * CB;
        float s = 0.f;
        for (int t = lane; t < CB; t += 32) { float v = c[t]; s += v * v; }
        #pragma unroll
        for (int o = 16; o > 0; o >>= 1) s += __shfl_xor_sync(0xffffffffu, s, o);
        if (lane == 0) g_cnorm[warp] = s;
    }
}

// ---------------------------------------------------------------------------
// Encoder: r0 = X @ W + b via 3-pair bf16 split on mma.sync (err ~1e-5 rel)
// CTA tile 128x128, 16 warps (4m x 4n), warp tile 32x32. 48 K-chunks of 64.
// 4-stage cp.async pipeline, one barrier per chunk. (identical to passing R16)
// ---------------------------------------------------------------------------
__global__ __launch_bounds__(512) void enc_mma_kernel(const float* __restrict__ encb) {
    extern __shared__ char dsm[];
    const uint32_t sb = smem_u32(dsm);
    const int tid = threadIdx.x, wid = tid >> 5, lane = tid & 31;
    const int wm = wid >> 2, wn = wid & 3;
    const int g = lane >> 2, q = lane & 3;
    const int m0 = blockIdx.y * 128, n0 = blockIdx.x * 128;

    const __nv_bfloat16* TA[3] = { g_X0, g_X0, g_X1 };
    const __nv_bfloat16* TB[3] = { g_W0, g_W1, g_W0 };

    float acc[2][4][4];
    #pragma unroll
    for (int i = 0; i < 2; i++)
        #pragma unroll
        for (int j = 0; j < 4; j++)
            #pragma unroll
            for (int k = 0; k < 4; k++) acc[i][j][k] = 0.f;

    auto issue = [&](int p) {
        int s = p & 3;
        int term = p >> 4, k0 = (p & 15) * 64;
        const __nv_bfloat16* As = TA[term];
        const __nv_bfloat16* Bs = TB[term];
        uint32_t ab = sb + s * 16384, bb = sb + 65536 + s * 16384;
        #pragma unroll
        for (int it = 0; it < 2; it++) {
            int w = tid + it * 512;
            int row = w >> 3, sg = w & 7;
            cpa16(ab + swz((uint32_t)(row * 128 + sg * 16)),
                  As + (size_t)(m0 + row) * DIN + k0 + sg * 8);
        }
        #pragma unroll
        for (int it = 0; it < 2; it++) {
            int w = tid + it * 512;
            int row = w >> 3, sg = w & 7;
            cpa16(bb + swz((uint32_t)(row * 128 + sg * 16)),
                  Bs + (size_t)(n0 + row) * DIN + k0 + sg * 8);
        }
        asm volatile("cp.async.commit_group;");
    };

    issue(0); issue(1); issue(2);

    #pragma unroll 1
    for (int p = 0; p < 48; p++) {
        WAIT_TAIL(p, 48);
        __syncthreads();
        if (p + 3 < 48) issue(p + 3);

        const uint32_t ab = sb + (p & 3) * 16384;
        const uint32_t bb = sb + 65536 + (p & 3) * 16384;
        #pragma unroll
        for (int kf = 0; kf < 4; kf++) {
            uint32_t af[2][4], bf[4][2];
            #pragma unroll
            for (int mf = 0; mf < 2; mf++) {
                int arow = wm * 32 + mf * 16 + (lane & 7) + ((lane >> 3) & 1) * 8;
                uint32_t koff = kf * 32 + (lane >> 4) * 16;
                ldmA(af[mf], ab + swz((uint32_t)(arow * 128) + koff));
            }
            #pragma unroll
            for (int np = 0; np < 2; np++) {
                uint32_t tmp[4];
                int nrow = wn * 32 + np * 16 + ((lane >> 4) & 1) * 8 + (lane & 7);
                uint32_t koff = kf * 32 + ((lane >> 3) & 1) * 16;
                ldmB4(tmp, bb + swz((uint32_t)(nrow * 128) + koff));
                bf[np * 2][0] = tmp[0]; bf[np * 2][1] = tmp[1];
                bf[np * 2 + 1][0] = tmp[2]; bf[np * 2 + 1][1] = tmp[3];
            }
            #pragma unroll
            for (int mf = 0; mf < 2; mf++)
                #pragma unroll
                for (int nf = 0; nf < 4; nf++)
                    mma16816(acc[mf][nf], af[mf], bf[nf]);
        }
    }

    // epilogue: bias + write fp32 residual and bf16 hi
    #pragma unroll
    for (int mf = 0; mf < 2; mf++) {
        #pragma unroll
        for (int nf = 0; nf < 4; nf++) {
            #pragma unroll
            for (int j = 0; j < 4; j++) {
                int row = m0 + wm * 32 + mf * 16 + g + (j >> 1) * 8;
                int col = n0 + wn * 32 + nf * 8 + q * 2 + (j & 1);
                float v = acc[mf][nf][j] + __ldg(&encb[col]);
                size_t o = (size_t)row * CB + col;
                g_residf[o] = v;
                g_Ahi[o]    = __float2bfloat16(v);
            }
        }
    }
}

// ---------------------------------------------------------------------------
// Fused 4-layer VQ kernel. Each CTA owns 128 rows for the whole chain.
// Per layer:
//   - reload A (bf16 residual hi) from g_Ahi via cp.async (8 x 16KB tiles)
//   - coarse bf16 scores (mma.sync): 32 chunks of 128 codes x 128 K-elems,
//     3-stage B pipeline (32KB/stage), ONE barrier per chunk
//   - per-thread top-3, dump into red smem (aliases A region)
//   - exact fp32 rescore within margin (reads g_residf)
//   - residual update: fp32 -> g_residf, bf16 hi -> g_Ahi (global)
// smem: A 8x16KB = 128KB | B 3x32KB = 96KB  (total 229376 <= 227KB limit)
// ---------------------------------------------------------------------------
__global__ __launch_bounds__(512) void vq_fused_kernel(const float* __restrict__ cbs) {
    extern __shared__ char dsm[];
    const uint32_t sb    = smem_u32(dsm);
    const uint32_t A_off = sb;                       // 8 tiles x 16KB
    const uint32_t B_off = sb + 131072;              // 3 stages x 32KB
    float* red_d = (float*)dsm;                      // [128][48] aliases A
    int*   red_i = (int*)(dsm + 128 * 48 * 4);       // [128][48] aliases A
    __shared__ int bsel[128];

    const int tid = threadIdx.x, wid = tid >> 5, lane = tid & 31;
    const int wm = wid >> 2, wn = wid & 3;
    const int g = lane >> 2, q = lane & 3;
    const int m0 = blockIdx.x * 128;

    #pragma unroll 1
    for (int layer = 0; layer < NL; layer++) {
        const __nv_bfloat16* Chi = g_Chi + (size_t)layer * NK * CB;
        const float* cn  = g_cnorm + layer * NK;
        const float* CbL = cbs + (size_t)layer * NK * CB;

        // A load from g_Ahi: one commit group
        #pragma unroll 1
        for (int it = 0; it < 16; it++) {
            int s = tid + it * 512;
            int tile = s >> 10, w = s & 1023;
            int row = w >> 3, sg = w & 7;
            cpa16(A_off + tile * 16384 + swz((uint32_t)(row * 128 + sg * 16)),
                  g_Ahi + (size_t)(m0 + row) * CB + tile * 64 + sg * 8);
        }
        asm volatile("cp.async.commit_group;");

        // chunk c: nt = c>>2 (code tile), kc2 = c&3 (128 K-elems = 2 halves)
        auto issueB = [&](int c) {
            uint32_t bbase = B_off + (uint32_t)(c % 3) * 32768;
            int nt = c >> 2, kc2 = c & 3;
            #pragma unroll
            for (int it = 0; it < 4; it++) {
                int s = tid + it * 512;               // 0..2047 sectors
                int half = s >> 10, w = s & 1023;
                int row = w >> 3, sg = w & 7;
                cpa16(bbase + (uint32_t)half * 16384 + swz((uint32_t)(row * 128 + sg * 16)),
                      Chi + (size_t)(nt * 128 + row) * CB + kc2 * 128 + half * 64 + sg * 8);
            }
            asm volatile("cp.async.commit_group;");
        };

        issueB(0); issueB(1);

        float t3d[4][3]; int t3i[4][3];
        #pragma unroll
        for (int r = 0; r < 4; r++) {
            t3d[r][0] = t3d[r][1] = t3d[r][2] = 3.4e38f;
            t3i[r][0] = t3i[r][1] = t3i[r][2] = 0;
        }

        float acc[2][4][4];

        #pragma unroll 1
        for (int p = 0; p < 32; p++) {
            const int nt = p >> 2, kc2 = p & 3;
            // pending groups at top: load p (must finish), load p+1 (may run)
            if (p == 31) asm volatile("cp.async.wait_group 0;" ::: "memory");
            else         asm volatile("cp.async.wait_group 1;" ::: "memory");
            __syncthreads();
            // stage (p+2)%3 was consumed at chunk p-1; its readers passed the
            // barrier above, so refilling it now is race-free.
            if (p + 2 < 32) issueB(p + 2);

            if (kc2 == 0) {
                #pragma unroll
                for (int i = 0; i < 2; i++)
                    #pragma unroll
                    for (int j = 0; j < 4; j++)
                        #pragma unroll
                        for (int k = 0; k < 4; k++) acc[i][j][k] = 0.f;
            }

            #pragma unroll
            for (int h = 0; h < 2; h++) {
                const uint32_t ab = A_off + (uint32_t)(kc2 * 2 + h) * 16384;
                const uint32_t bb = B_off + (uint32_t)(p % 3) * 32768 + (uint32_t)h * 16384;
                #pragma unroll
                for (int kf = 0; kf < 4; kf++) {
                    uint32_t af[2][4], bf[4][2];
                    #pragma unroll
                    for (int mf = 0; mf < 2; mf++) {
                        int arow = wm * 32 + mf * 16 + (lane & 7) + ((lane >> 3) & 1) * 8;
                        uint32_t koff = kf * 32 + (lane >> 4) * 16;
                        ldmA(af[mf], ab + swz((uint32_t)(arow * 128) + koff));
                    }
                    #pragma unroll
                    for (int np = 0; np < 2; np++) {
                        uint32_t tmp[4];
                        int nrow = wn * 32 + np * 16 + ((lane >> 4) & 1) * 8 + (lane & 7);
                        uint32_t koff = kf * 32 + ((lane >> 3) & 1) * 16;
                        ldmB4(tmp, bb + swz((uint32_t)(nrow * 128) + koff));
                        bf[np * 2][0] = tmp[0]; bf[np * 2][1] = tmp[1];
                        bf[np * 2 + 1][0] = tmp[2]; bf[np * 2 + 1][1] = tmp[3];
                    }
                    #pragma unroll
                    for (int mf = 0; mf < 2; mf++)
                        #pragma unroll
                        for (int nf = 0; nf < 4; nf++)
                            mma16816(acc[mf][nf], af[mf], bf[nf]);
                }
            }

            if (kc2 == 3) {   // code tile complete: fold into per-thread top-3
                #pragma unroll
                for (int mf = 0; mf < 2; mf++) {
                    #pragma unroll
                    for (int nf = 0; nf < 4; nf++) {
                        int colbase = nt * 128 + wn * 32 + nf * 8 + q * 2;
                        #pragma unroll
                        for (int j = 0; j < 4; j++) {
                            int code = colbase + (j & 1);
                            float d = __ldg(&cn[code]) - 2.f * acc[mf][nf][j];
                            int rs = mf * 2 + (j >> 1);
                            if (d < t3d[rs][2]) {
                                if (d < t3d[rs][1]) {
                                    t3d[rs][2] = t3d[rs][1]; t3i[rs][2] = t3i[rs][1];
                                    if (d < t3d[rs][0]) {
                                        t3d[rs][1] = t3d[rs][0]; t3i[rs][1] = t3i[rs][0];
                                        t3d[rs][0] = d; t3i[rs][0] = code;
                                    } else { t3d[rs][1] = d; t3i[rs][1] = code; }
                                } else { t3d[rs][2] = d; t3i[rs][2] = code; }
                            }
                        }
                    }
                }
            }
        }
        __syncthreads();   // all MMA/A reads done before red aliases A region

        // dump per-owner top-3 (A smem region is free; reloaded next layer)
        #pragma unroll
        for (int rs = 0; rs < 4; rs++) {
            int mf = rs >> 1, h = rs & 1;
            int row = wm * 32 + mf * 16 + g + h * 8;
            int owner = wn * 4 + q;           // 0..15
            #pragma unroll
            for (int j = 0; j < 3; j++) {
                red_d[row * 48 + owner * 3 + j] = t3d[rs][j];
                red_i[row * 48 + owner * 3 + j] = t3i[rs][j];
            }
        }
        __syncthreads();

        // exact fp32 rescore within margin of coarse min: 4 threads per row
        {
            int row = tid >> 2, sub = tid & 3;
            const float* rd = red_d + row * 48;
            const int*   ri = red_i + row * 48;
            float lmin = 3.4e38f;
            #pragma unroll 1
            for (int e = sub * 12; e < sub * 12 + 12; e++) lmin = fminf(lmin, rd[e]);
            #pragma unroll
            for (int o = 1; o < 4; o <<= 1)
                lmin = fminf(lmin, __shfl_xor_sync(0xffffffffu, lmin, o));
            const float TAU = 1.5f;
            float bd = 3.4e38f; int bi = 0x7fffffff;
            const float* R = g_residf + (size_t)(m0 + row) * CB;
            #pragma unroll 1
            for (int e = sub * 12; e < sub * 12 + 12; e++) {
                if (rd[e] <= lmin + TAU) {
                    int c = ri[e];
                    const float* C = CbL + (size_t)c * CB;
                    float s0 = 0.f, s1 = 0.f, s2 = 0.f, s3 = 0.f;
                    #pragma unroll 4
                    for (int k = 0; k < CB; k += 4) {
                        s0 += R[k]     * C[k];
                        s1 += R[k + 1] * C[k + 1];
                        s2 += R[k + 2] * C[k + 2];
                        s3 += R[k + 3] * C[k + 3];
                    }
                    float de = __ldg(&cn[c]) - 2.f * ((s0 + s1) + (s2 + s3));
                    if (de < bd || (de == bd && c < bi)) { bd = de; bi = c; }
                }
            }
            #pragma unroll
            for (int o = 1; o < 4; o <<= 1) {
                float od = __shfl_xor_sync(0xffffffffu, bd, o);
                int   oi = __shfl_xor_sync(0xffffffffu, bi, o);
                if (od < bd || (od == bd && oi < bi)) { bd = od; bi = oi; }
            }
            if (sub == 0) {
                bsel[row] = bi;
                g_ids[(size_t)(m0 + row) * NL + layer] = bi;
            }
        }
        __syncthreads();

        // residual -= codebook[best]; fp32 + bf16 hi both to GLOBAL
        #pragma unroll 1
        for (int e = tid; e < 128 * (CB / 4); e += 512) {
            int r = e >> 7, c4 = (e & 127) * 4;
            int ci = bsel[r];
            size_t ro = (size_t)(m0 + r) * CB + c4;
            float4 rv = *(float4*)&g_residf[ro];
            float4 cv = *(const float4*)&CbL[(size_t)ci * CB + c4];
            rv.x -= cv.x; rv.y -= cv.y; rv.z -= cv.z; rv.w -= cv.w;
            *(float4*)&g_residf[ro] = rv;
            if (layer < NL - 1) {
                __nv_bfloat162 h0{__float2bfloat16(rv.x), __float2bfloat16(rv.y)};
                __nv_bfloat162 h1{__float2bfloat16(rv.z), __float2bfloat16(rv.w)};
                *(__nv_bfloat162*)&g_Ahi[ro]     = h0;
                *(__nv_bfloat162*)&g_Ahi[ro + 2] = h1;
            }
        }
        __syncthreads();   // g_Ahi writes visible before next layer's A load
    }
}

// ---------------------------------------------------------------------------
// Decoder + ids output (exact)
// ---------------------------------------------------------------------------
__global__ void decode_kernel(const float* __restrict__ dec_W,
                              const float* __restrict__ dec_b,
                              float* __restrict__ out) {
    int idx = blockIdx.x * blockDim.x + threadIdx.x;
    if (idx >= NB * CB) return;
    int b = idx / CB, j = idx % CB;
    const int* ids = &g_ids[b * NL];
    float s = dec_b[j];
    #pragma unroll
    for (int l = 0; l < NL; l++)
        s += (float)ids[l] * dec_W[l * CB + j];
    out[idx] = s;
}

__global__ void ids_out_kernel(float* __restrict__ out, int n) {
    int idx = blockIdx.x * blockDim.x + threadIdx.x;
    if (idx < n) out[idx] = (float)g_ids[idx];
}

// ---------------------------------------------------------------------------
extern "C" void kernel_launch(void* const* d_in, const int* in_sizes, int n_in,
                              void* d_out, int out_size) {
    (void)in_sizes; (void)n_in;
    const float* X    = (const float*)d_in[0];
    const float* encW = (const float*)d_in[1];
    const float* encb = (const float*)d_in[2];
    const float* cbs  = (const float*)d_in[3];
    const float* decW = (const float*)d_in[4];
    const float* decb = (const float*)d_in[5];
    float* out = (float*)d_out;

    const int VQ_SMEM  = 131072 + 3 * 32768;   // 229376 (<= 227KB limit)
    const int ENC_SMEM = 8 * 16384;            // 131072
    cudaFuncSetAttribute(vq_fused_kernel, cudaFuncAttributeMaxDynamicSharedMemorySize, VQ_SMEM);
    cudaFuncSetAttribute(enc_mma_kernel,  cudaFuncAttributeMaxDynamicSharedMemorySize, ENC_SMEM);

    // prep (2 launches)
    split_xw_kernel<<<(NB * DIN + 255) / 256, 256>>>(X, encW);
    prep_cb_kernel<<<(NL * NK * CB + 255) / 256, 256>>>(cbs);

    // encoder (tensor cores, 3-pair split)
    dim3 gEnc(CB / 128, NB / 128);
    enc_mma_kernel<<<gEnc, 512, ENC_SMEM>>>(encb);

    // fused 4-layer VQ (tensor-core coarse + exact rescore)
    vq_fused_kernel<<<NB / 128, 512, VQ_SMEM>>>(cbs);

    const long long RE = (long long)NB * CB;   // 8388608
    const long long ID = (long long)NB * NL;   // 65536

    if ((long long)out_size >= RE) {
        decode_kernel<<<(NB * CB + 255) / 256, 256>>>(decW, decb, out);
        if ((long long)out_size >= RE + ID)
            ids_out_kernel<<<(int)((ID + 255) / 256), 256>>>(out + RE, (int)ID);
    } else {
        ids_out_kernel<<<(out_size + 255) / 256, 256>>>(out, out_size);
    }
}